// round 16
// baseline (speedup 1.0000x reference)
#include <cuda_runtime.h>
#include <cuda_fp16.h>
#include <cstdint>

// dw[p][q] = LR * ( (1/B)*sum_b post[b][p]*pre[b][q] - WD*W[p][q] )
// B=128, P=Q=1024.  fp16 single-pass mma.sync (rel err ~3e-5).
// R16: R12 base (single launch, coalesced layout-preserving convert,
// trans-ldmatrix, fused epilogue) + software-pipelined mainloop (fragment
// double buffering: next iteration's LDSMs issued before current MMAs) and
// streaming (.wt) output stores.

#define DIM      1024
#define KDIM     128
#define NTHREADS 512
#define BM       128
#define BN       64

#define PA       272                  // fp16 A tile pitch (256 data + 16 pad)
#define PB       144                  // fp16 B tile pitch (128 data + 16 pad)
#define FA       0
#define FB       (KDIM * PA)          // 34816
#define SMEM_TOTAL (FB + KDIM * PB)   // 53248

static __device__ __forceinline__ uint32_t smem_u32(const void* p) {
    uint32_t a;
    asm("{ .reg .u64 t; cvta.to.shared.u64 t, %1; cvt.u32.u64 %0, t; }" : "=r"(a) : "l"(p));
    return a;
}
static __device__ __forceinline__ void ldsm_x4_trans(uint32_t* r, uint32_t addr) {
    asm volatile("ldmatrix.sync.aligned.m8n8.x4.trans.shared.b16 {%0,%1,%2,%3}, [%4];"
                 : "=r"(r[0]), "=r"(r[1]), "=r"(r[2]), "=r"(r[3]) : "r"(addr));
}
static __device__ __forceinline__ void mma16816(float* c, const uint32_t* a,
                                                uint32_t b0, uint32_t b1) {
    asm volatile(
        "mma.sync.aligned.m16n8k16.row.col.f32.f16.f16.f32 "
        "{%0,%1,%2,%3}, {%4,%5,%6,%7}, {%8,%9}, {%0,%1,%2,%3};"
        : "+f"(c[0]), "+f"(c[1]), "+f"(c[2]), "+f"(c[3])
        : "r"(a[0]), "r"(a[1]), "r"(a[2]), "r"(a[3]), "r"(b0), "r"(b1));
}
static __device__ __forceinline__ uint32_t pack_h2(float a, float b) {
    const __half2 h = __floats2half2_rn(a, b);
    return *(const uint32_t*)&h;
}
static __device__ __forceinline__ void stg_wt_64(void* gaddr, float x, float y) {
    asm volatile("st.global.wt.v2.f32 [%0], {%1, %2};" :: "l"(gaddr), "f"(x), "f"(y)
                 : "memory");
}

__global__ __launch_bounds__(NTHREADS, 1)
void hebbian_fp16_kernel(const float* __restrict__ pre,
                         const float* __restrict__ post,
                         const float* __restrict__ W,
                         float* __restrict__ out)
{
    extern __shared__ char smem[];
    const uint32_t sbase = smem_u32(smem);
    const int tid  = threadIdx.x;
    const int lane = tid & 31;
    const int wid  = tid >> 5;
    const int pm0  = blockIdx.y * BM;
    const int qn0  = blockIdx.x * BN;

    // warp tiling: 8(m) x 2(n), warp tile m16 x n32
    const int wm = (wid >> 1) * 16;
    const int wn = (wid & 1) * 32;
    const int prow = pm0 + wm + (lane >> 2);
    const int qcol = qn0 + wn + (lane & 3) * 2;

    // ---- W prefetch first (longest latency; drains during convert) ----
    float2 wv[4][2];
    #pragma unroll
    for (int nn = 0; nn < 4; ++nn) {
        const int q = qcol + nn * 8;
        wv[nn][0] = *(const float2*)(W + (size_t)prow * DIM + q);
        wv[nn][1] = *(const float2*)(W + (size_t)(prow + 8) * DIM + q);
    }

    // ---- issue ALL convert loads (coalesced LDG.128 along m), max MLP ----
    float4 va[8];                          // A: 128k x 32 groups = 4096 units
    #pragma unroll
    for (int it = 0; it < 8; ++it) {
        const int u = tid + NTHREADS * it;
        const int k = u >> 5;
        const int f = u & 31;
        va[it] = *(const float4*)(post + (size_t)k * DIM + pm0 + f * 4);
    }
    float4 vb[4];                          // B: 128k x 16 groups = 2048 units
    #pragma unroll
    for (int it = 0; it < 4; ++it) {
        const int u = tid + NTHREADS * it;
        const int k = u >> 4;
        const int f = u & 15;
        vb[it] = *(const float4*)(pre + (size_t)k * DIM + qn0 + f * 4);
    }

    // ---- convert + store fp16 tiles (layout-preserving, conflict-free) ----
    #pragma unroll
    for (int it = 0; it < 8; ++it) {
        const int u = tid + NTHREADS * it;
        const int k = u >> 5;
        const int f = u & 31;
        uint2 o;
        o.x = pack_h2(va[it].x, va[it].y);
        o.y = pack_h2(va[it].z, va[it].w);
        *(uint2*)(smem + FA + k * PA + f * 8) = o;
    }
    #pragma unroll
    for (int it = 0; it < 4; ++it) {
        const int u = tid + NTHREADS * it;
        const int k = u >> 4;
        const int f = u & 15;
        uint2 o;
        o.x = pack_h2(vb[it].x, vb[it].y);
        o.y = pack_h2(vb[it].z, vb[it].w);
        *(uint2*)(smem + FB + k * PB + f * 8) = o;
    }
    __syncthreads();

    // ---- software-pipelined mainloop (fragment double buffering) ----
    float acc[4][4];
    #pragma unroll
    for (int j = 0; j < 4; ++j)
        #pragma unroll
        for (int r = 0; r < 4; ++r)
            acc[j][r] = 0.0f;

    const int kl = (lane & 7) + ((lane >> 4) << 3);   // k row within 16-block
    const int ml = (lane & 8);                        // m/n sub-tile select
    const uint32_t abase = sbase + FA + kl * PA + (wm + ml) * 2;
    const uint32_t bbase = sbase + FB + kl * PB + (wn + ml) * 2;

    uint32_t a[2][4], b[2][2][4];
    ldsm_x4_trans(a[0], abase);
    ldsm_x4_trans(b[0][0], bbase);
    ldsm_x4_trans(b[0][1], bbase + 16 * 2);           // wn + 16 sub-block

    #pragma unroll
    for (int ks = 0; ks < KDIM / 16; ++ks) {
        const int cur = ks & 1, nxt = cur ^ 1;
        if (ks < KDIM / 16 - 1) {
            const uint32_t koff = (uint32_t)(ks + 1) * 16;
            ldsm_x4_trans(a[nxt], abase + koff * PA);
            ldsm_x4_trans(b[nxt][0], bbase + koff * PB);
            ldsm_x4_trans(b[nxt][1], bbase + koff * PB + 16 * 2);
        }
        #pragma unroll
        for (int nn = 0; nn < 4; ++nn) {
            const int nb = nn >> 1, sel = nn & 1;
            mma16816(acc[nn], a[cur], b[cur][nb][sel], b[cur][nb][sel + 2]);
        }
    }

    // ---- fused epilogue: dw = acc*(LR/B) - (LR*WD)*W, streaming stores ----
    const float c1 = 0.005f / 128.0f;
    const float c2 = 0.005f * 0.0001f;
    #pragma unroll
    for (int nn = 0; nn < 4; ++nn) {
        const int q = qcol + nn * 8;
        #pragma unroll
        for (int h = 0; h < 2; ++h) {
            const int p = prow + h * 8;
            stg_wt_64(out + (size_t)p * DIM + q,
                      fmaf(acc[nn][2 * h + 0], c1, -c2 * wv[nn][h].x),
                      fmaf(acc[nn][2 * h + 1], c1, -c2 * wv[nn][h].y));
        }
    }
}

extern "C" void kernel_launch(void* const* d_in, const int* in_sizes, int n_in,
                              void* d_out, int out_size)
{
    const float* pre  = (const float*)d_in[0];   // (128, 1024)
    const float* post = (const float*)d_in[1];   // (128, 1024)
    const float* W    = (const float*)d_in[2];   // (1024, 1024)
    float* out = (float*)d_out;                  // (1024, 1024)

    static bool attr_set = false;
    if (!attr_set) {
        cudaFuncSetAttribute(hebbian_fp16_kernel,
                             cudaFuncAttributeMaxDynamicSharedMemorySize, SMEM_TOTAL);
        attr_set = true;
    }
    dim3 grid(DIM / BN, DIM / BM);   // (16, 8) = 128 CTAs, 1/SM, single wave
    hebbian_fp16_kernel<<<grid, NTHREADS, SMEM_TOTAL>>>(pre, post, W, out);
}

// round 17
// speedup vs baseline: 1.0372x; 1.0372x over previous
#include <cuda_runtime.h>
#include <cuda_fp16.h>
#include <cstdint>

// dw[p][q] = LR * ( (1/B)*sum_b post[b][p]*pre[b][q] - WD*W[p][q] )
// B=128, P=Q=1024.  fp16 single-pass mma.sync (rel err ~3e-5).
// R17 (final consolidation of the measured-best R12 structure):
//  - single launch, 128 CTAs (1/SM), 512 threads
//  - operand LDG.128 issued FIRST (gate the mainloop), W prefetch second
//    (needed only in the epilogue, drains under the mainloop)
//  - layout-preserving fp32->fp16 convert (coalesced; transpose happens
//    inside ldmatrix.x4.trans)
//  - verified trans-ldmatrix m16xn32 warp-tile mainloop
//  - fused weight-decay epilogue from registers

#define DIM      1024
#define KDIM     128
#define NTHREADS 512
#define BM       128
#define BN       64

#define PA       272                  // fp16 A tile pitch (256 data + 16 pad)
#define PB       144                  // fp16 B tile pitch (128 data + 16 pad)
#define FA       0
#define FB       (KDIM * PA)          // 34816
#define SMEM_TOTAL (FB + KDIM * PB)   // 53248

static __device__ __forceinline__ uint32_t smem_u32(const void* p) {
    uint32_t a;
    asm("{ .reg .u64 t; cvta.to.shared.u64 t, %1; cvt.u32.u64 %0, t; }" : "=r"(a) : "l"(p));
    return a;
}
static __device__ __forceinline__ void ldsm_x4_trans(uint32_t* r, uint32_t addr) {
    asm volatile("ldmatrix.sync.aligned.m8n8.x4.trans.shared.b16 {%0,%1,%2,%3}, [%4];"
                 : "=r"(r[0]), "=r"(r[1]), "=r"(r[2]), "=r"(r[3]) : "r"(addr));
}
static __device__ __forceinline__ void mma16816(float* c, const uint32_t* a,
                                                uint32_t b0, uint32_t b1) {
    asm volatile(
        "mma.sync.aligned.m16n8k16.row.col.f32.f16.f16.f32 "
        "{%0,%1,%2,%3}, {%4,%5,%6,%7}, {%8,%9}, {%0,%1,%2,%3};"
        : "+f"(c[0]), "+f"(c[1]), "+f"(c[2]), "+f"(c[3])
        : "r"(a[0]), "r"(a[1]), "r"(a[2]), "r"(a[3]), "r"(b0), "r"(b1));
}
static __device__ __forceinline__ uint32_t pack_h2(float a, float b) {
    const __half2 h = __floats2half2_rn(a, b);
    return *(const uint32_t*)&h;
}

__global__ __launch_bounds__(NTHREADS, 1)
void hebbian_fp16_kernel(const float* __restrict__ pre,
                         const float* __restrict__ post,
                         const float* __restrict__ W,
                         float* __restrict__ out)
{
    extern __shared__ char smem[];
    const uint32_t sbase = smem_u32(smem);
    const int tid  = threadIdx.x;
    const int lane = tid & 31;
    const int wid  = tid >> 5;
    const int pm0  = blockIdx.y * BM;
    const int qn0  = blockIdx.x * BN;

    // warp tiling: 8(m) x 2(n), warp tile m16 x n32
    const int wm = (wid >> 1) * 16;
    const int wn = (wid & 1) * 32;
    const int prow = pm0 + wm + (lane >> 2);
    const int qcol = qn0 + wn + (lane & 3) * 2;

    // ---- operand loads FIRST (they gate the mainloop barrier) ----
    float4 va[8];                          // A: 128k x 32 groups = 4096 units
    #pragma unroll
    for (int it = 0; it < 8; ++it) {
        const int u = tid + NTHREADS * it;
        const int k = u >> 5;
        const int f = u & 31;
        va[it] = *(const float4*)(post + (size_t)k * DIM + pm0 + f * 4);
    }
    float4 vb[4];                          // B: 128k x 16 groups = 2048 units
    #pragma unroll
    for (int it = 0; it < 4; ++it) {
        const int u = tid + NTHREADS * it;
        const int k = u >> 4;
        const int f = u & 15;
        vb[it] = *(const float4*)(pre + (size_t)k * DIM + qn0 + f * 4);
    }

    // ---- W prefetch second (epilogue-only; drains under the mainloop) ----
    float2 wv[4][2];
    #pragma unroll
    for (int nn = 0; nn < 4; ++nn) {
        const int q = qcol + nn * 8;
        wv[nn][0] = *(const float2*)(W + (size_t)prow * DIM + q);
        wv[nn][1] = *(const float2*)(W + (size_t)(prow + 8) * DIM + q);
    }

    // ---- convert + store fp16 tiles (layout-preserving, conflict-free) ----
    #pragma unroll
    for (int it = 0; it < 8; ++it) {
        const int u = tid + NTHREADS * it;
        const int k = u >> 5;
        const int f = u & 31;
        uint2 o;
        o.x = pack_h2(va[it].x, va[it].y);
        o.y = pack_h2(va[it].z, va[it].w);
        *(uint2*)(smem + FA + k * PA + f * 8) = o;
    }
    #pragma unroll
    for (int it = 0; it < 4; ++it) {
        const int u = tid + NTHREADS * it;
        const int k = u >> 4;
        const int f = u & 15;
        uint2 o;
        o.x = pack_h2(vb[it].x, vb[it].y);
        o.y = pack_h2(vb[it].z, vb[it].w);
        *(uint2*)(smem + FB + k * PB + f * 8) = o;
    }
    __syncthreads();

    // ---- mma mainloop (verified trans-ldmatrix scheme) ----
    float acc[4][4];
    #pragma unroll
    for (int j = 0; j < 4; ++j)
        #pragma unroll
        for (int r = 0; r < 4; ++r)
            acc[j][r] = 0.0f;

    const int kl = (lane & 7) + ((lane >> 4) << 3);   // k row within 16-block
    const int ml = (lane & 8);                        // m/n sub-tile select

    #pragma unroll
    for (int ks = 0; ks < KDIM / 16; ++ks) {
        const int kb = ks * 16;
        uint32_t a[4], b[2][4];
        ldsm_x4_trans(a, sbase + FA + (kb + kl) * PA + (wm + ml) * 2);
        #pragma unroll
        for (int nb = 0; nb < 2; ++nb)
            ldsm_x4_trans(b[nb], sbase + FB + (kb + kl) * PB + (wn + nb * 16 + ml) * 2);
        #pragma unroll
        for (int nn = 0; nn < 4; ++nn) {
            const int nb = nn >> 1, sel = nn & 1;
            mma16816(acc[nn], a, b[nb][sel], b[nb][sel + 2]);
        }
    }

    // ---- fused epilogue: dw = acc*(LR/B) - (LR*WD)*W (W already in regs) ----
    const float c1 = 0.005f / 128.0f;
    const float c2 = 0.005f * 0.0001f;
    #pragma unroll
    for (int nn = 0; nn < 4; ++nn) {
        const int q = qcol + nn * 8;
        #pragma unroll
        for (int h = 0; h < 2; ++h) {
            const int p = prow + h * 8;
            float2 o;
            o.x = fmaf(acc[nn][2 * h + 0], c1, -c2 * wv[nn][h].x);
            o.y = fmaf(acc[nn][2 * h + 1], c1, -c2 * wv[nn][h].y);
            *(float2*)(out + (size_t)p * DIM + q) = o;
        }
    }
}

extern "C" void kernel_launch(void* const* d_in, const int* in_sizes, int n_in,
                              void* d_out, int out_size)
{
    const float* pre  = (const float*)d_in[0];   // (128, 1024)
    const float* post = (const float*)d_in[1];   // (128, 1024)
    const float* W    = (const float*)d_in[2];   // (1024, 1024)
    float* out = (float*)d_out;                  // (1024, 1024)

    static bool attr_set = false;
    if (!attr_set) {
        cudaFuncSetAttribute(hebbian_fp16_kernel,
                             cudaFuncAttributeMaxDynamicSharedMemorySize, SMEM_TOTAL);
        attr_set = true;
    }
    dim3 grid(DIM / BN, DIM / BM);   // (16, 8) = 128 CTAs, 1/SM, single wave
    hebbian_fp16_kernel<<<grid, NTHREADS, SMEM_TOTAL>>>(pre, post, W, out);
}